// round 2
// baseline (speedup 1.0000x reference)
#include <cuda_runtime.h>

// Problem constants (fixed by the reference setup)
#define SDIM 8192
#define CIN  32
#define COUT 8
#define BDIM 128
#define STILE 32          // s positions per block
#define NTHREADS 256      // 32 s-lanes x 8 b-threads

// Fast accurate tanh: 2 MUFU (EX2 + RCP) + a few FMA. Abs err ~1e-7,
// saturates correctly for |x| large (exp -> 0 or inf).
__device__ __forceinline__ float ftanh(float v) {
    float e = __expf(2.0f * v);
    return 1.0f - __fdividef(2.0f, e + 1.0f);
}

__global__ __launch_bounds__(NTHREADS, 2)
void lc3_fused_kernel(const float* __restrict__ x,
                      const float* __restrict__ w1,
                      const float* __restrict__ w2,
                      const float* __restrict__ bias,
                      float* __restrict__ out) {
    // Smem: w2 tile laid out [(j*8+o)*32 + sl]  -> lane-consecutive, conflict-free
    __shared__ float s_w2[CIN * COUT * STILE];   // 32 KB
    __shared__ float s_ws[CIN * STILE];          // 4 KB  (wsum[j][sl])

    const int tid = threadIdx.x;
    const int sl  = tid & 31;        // s lane within tile
    const int bt  = tid >> 5;        // b-thread group 0..7
    const int s0  = blockIdx.x * STILE;
    const int sg  = s0 + sl;

    // ---- Stage w2 slice into smem (8192 floats, fully coalesced) ----
    #pragma unroll
    for (int p = 0; p < (CIN * COUT * STILE) / NTHREADS; p++) {
        int lin = p * NTHREADS + tid;          // = (j*8+o)*32 + sl2
        int jo  = lin >> 5;
        int sl2 = lin & 31;
        int j   = jo >> 3;
        int o   = jo & 7;
        s_w2[lin] = w2[(o * CIN + j) * SDIM + s0 + sl2];
    }

    // ---- Reduce w1 over i -> wsum[j][s] in smem (w1 read exactly once) ----
    #pragma unroll
    for (int p = 0; p < (CIN * STILE) / NTHREADS; p++) {
        int lin = p * NTHREADS + tid;          // = j*32 + sl2
        int j   = lin >> 5;
        int sl2 = lin & 31;
        const float* wp = w1 + j * SDIM + s0 + sl2;
        float acc = 0.0f;
        #pragma unroll
        for (int i = 0; i < CIN; i++)
            acc += wp[i * (CIN * SDIM)];
        s_ws[lin] = acc;
    }

    // bias in registers (per-thread, shared across all b iterations)
    float bia[COUT];
    #pragma unroll
    for (int o = 0; o < COUT; o++)
        bia[o] = bias[o * SDIM + sg];

    __syncthreads();

    // ---- Main loop: each thread handles 16 b values, 2 per iteration ----
    for (int ib = 0; ib < 8; ib++) {
        const int b0 = bt * 16 + 2 * ib;       // this thread's pair of b rows

        float h0[CIN], h1[CIN];
        const float* x0p = x + (b0      * CIN) * SDIM + sg;
        const float* x1p = x + ((b0 + 1) * CIN) * SDIM + sg;
        #pragma unroll
        for (int j = 0; j < CIN; j++) {
            float ws = s_ws[j * 32 + sl];
            float v0 = x0p[j * SDIM];
            float v1 = x1p[j * SDIM];
            h0[j] = ftanh(v0 * ws);
            h1[j] = ftanh(v1 * ws);
        }

        float a0[COUT], a1[COUT];
        #pragma unroll
        for (int o = 0; o < COUT; o++) { a0[o] = bia[o]; a1[o] = bia[o]; }

        #pragma unroll
        for (int j = 0; j < CIN; j++) {
            #pragma unroll
            for (int o = 0; o < COUT; o++) {
                float w = s_w2[(j * 8 + o) * 32 + sl];
                a0[o] = fmaf(h0[j], w, a0[o]);
                a1[o] = fmaf(h1[j], w, a1[o]);
            }
        }

        float* o0p = out + (b0      * COUT) * SDIM + sg;
        float* o1p = out + ((b0 + 1) * COUT) * SDIM + sg;
        #pragma unroll
        for (int o = 0; o < COUT; o++) {
            o0p[o * SDIM] = ftanh(a0[o]);
            o1p[o * SDIM] = ftanh(a1[o]);
        }
    }
}

extern "C" void kernel_launch(void* const* d_in, const int* in_sizes, int n_in,
                              void* d_out, int out_size) {
    const float* x    = (const float*)d_in[0];
    const float* w1   = (const float*)d_in[1];
    const float* w2   = (const float*)d_in[2];
    const float* bias = (const float*)d_in[3];
    float* out = (float*)d_out;

    dim3 grid(SDIM / STILE);   // 256 blocks, one wave at 2 blocks/SM
    dim3 block(NTHREADS);
    lc3_fused_kernel<<<grid, block>>>(x, w1, w2, bias, out);
}